// round 14
// baseline (speedup 1.0000x reference)
#include <cuda_runtime.h>
#include <cuda_bf16.h>
#include <cstdint>

#define S_LEN 1024
#define DHDIM 64
#define NHEADS 8
#define NBATCH 4
#define BHN (NBATCH * NHEADS)
#define LDA 40

// attn smem layout (bytes)
#define OFF_QE 0            // [128][152] bf16 = 38912 (per-warp shifted windows)
#define QE_STRIDE 152
#define OFF_K 38912         // 2 stages x (Kh 18432 + Kl 18432)
#define OFF_REL 112640      // 2 stages x 36864 ([256][72])
#define OFF_V 186368        // Vh 17408 + Vl 17408 ([64][136])
#define ATTN_SMEM 221184

// ---------------- scratch ----------------
__device__ __nv_bfloat16 g_Ahi[4096 * 512];
__device__ __nv_bfloat16 g_Alo[4096 * 512];
__device__ __nv_bfloat16 g_A0h[4096 * 512];
__device__ __nv_bfloat16 g_A0l[4096 * 512];
__device__ __nv_bfloat16 g_A1h[4096 * 512];
__device__ __nv_bfloat16 g_A1l[4096 * 512];
__device__ __nv_bfloat16 g_A2h[4096 * 512];
__device__ __nv_bfloat16 g_A2l[4096 * 512];
__device__ __nv_bfloat16 g_Whi[4 * 512 * 512];
__device__ __nv_bfloat16 g_Wlo[4 * 512 * 512];
__device__ __nv_bfloat16 g_Qh[BHN * S_LEN * DHDIM];
__device__ __nv_bfloat16 g_Ql[BHN * S_LEN * DHDIM];
__device__ __nv_bfloat16 g_Kh[BHN * S_LEN * DHDIM];
__device__ __nv_bfloat16 g_Kl[BHN * S_LEN * DHDIM];
__device__ __nv_bfloat16 g_Vth[BHN * DHDIM * S_LEN];     // [bh][d][t]
__device__ __nv_bfloat16 g_Vtl[BHN * DHDIM * S_LEN];
__device__ __nv_bfloat16 g_relT[NHEADS * S_LEN * DHDIM]; // [h][l][d]

// ---------------- helpers ----------------
__device__ __forceinline__ uint32_t smaddr(const void* p) {
    return (uint32_t)__cvta_generic_to_shared(p);
}
#define CP16(dst, src) \
    asm volatile("cp.async.cg.shared.global [%0], [%1], 16;" :: "r"(dst), "l"(src))
#define CP16P(dst, src, n) \
    asm volatile("cp.async.cg.shared.global [%0], [%1], 16, %2;" :: "r"(dst), "l"(src), "r"(n))
#define CP_COMMIT() asm volatile("cp.async.commit_group;")

__device__ __forceinline__ void ldm_x4(uint32_t* r, uint32_t a) {
    asm volatile("ldmatrix.sync.aligned.m8n8.x4.shared.b16 {%0,%1,%2,%3}, [%4];"
                 : "=r"(r[0]), "=r"(r[1]), "=r"(r[2]), "=r"(r[3]) : "r"(a));
}
__device__ __forceinline__ void mma16816(float* c, const uint32_t* a, const uint32_t* b) {
    asm volatile("mma.sync.aligned.m16n8k16.row.col.f32.bf16.bf16.f32 "
                 "{%0,%1,%2,%3}, {%4,%5,%6,%7}, {%8,%9}, {%0,%1,%2,%3};"
                 : "+f"(c[0]), "+f"(c[1]), "+f"(c[2]), "+f"(c[3])
                 : "r"(a[0]), "r"(a[1]), "r"(a[2]), "r"(a[3]), "r"(b[0]), "r"(b[1]));
}
__device__ __forceinline__ void split2(float v0, float v1,
                                       __nv_bfloat162& h2, __nv_bfloat162& l2) {
    __nv_bfloat16 h0 = __float2bfloat16(v0), h1 = __float2bfloat16(v1);
    h2 = __nv_bfloat162(h0, h1);
    l2 = __nv_bfloat162(__float2bfloat16(v0 - __bfloat162float(h0)),
                        __float2bfloat16(v1 - __bfloat162float(h1)));
}
__device__ __forceinline__ uint32_t pack_split(float v0, float v1, uint32_t& lo) {
    __nv_bfloat162 h2, l2;
    split2(v0, v1, h2, l2);
    lo = *(uint32_t*)&l2;
    return *(uint32_t*)&h2;
}

// ---------------- convert kernels ----------------
__global__ void conv_act3(const float* __restrict__ q, const float* __restrict__ k,
                          const float* __restrict__ v, int n4) {
    int i = blockIdx.x * blockDim.x + threadIdx.x;
    if (i >= n4) return;
    int w = blockIdx.y;
    const float* x = (w == 0) ? q : (w == 1) ? k : v;
    __nv_bfloat16* hi = (w == 0) ? g_A0h : (w == 1) ? g_A1h : g_A2h;
    __nv_bfloat16* lo = (w == 0) ? g_A0l : (w == 1) ? g_A1l : g_A2l;
    float4 val = ((const float4*)x)[i];
    __nv_bfloat162 h2a, l2a, h2b, l2b;
    split2(val.x, val.y, h2a, l2a);
    split2(val.z, val.w, h2b, l2b);
    ((__nv_bfloat162*)hi)[2 * i] = h2a; ((__nv_bfloat162*)hi)[2 * i + 1] = h2b;
    ((__nv_bfloat162*)lo)[2 * i] = l2a; ((__nv_bfloat162*)lo)[2 * i + 1] = l2b;
}

__global__ void conv_misc(const float* __restrict__ W0, const float* __restrict__ W1,
                          const float* __restrict__ W2, const float* __restrict__ W3,
                          const float* __restrict__ rel) {
    __shared__ float t[32][33];
    int z = blockIdx.z;
    int tx = threadIdx.x, ty = threadIdx.y;
    if (z < 4) {
        const float* W = (z == 0) ? W0 : (z == 1) ? W1 : (z == 2) ? W2 : W3;
        int bx = blockIdx.x, by = blockIdx.y;
#pragma unroll
        for (int j = 0; j < 32; j += 8)
            t[ty + j][tx] = W[(size_t)(by * 32 + ty + j) * 512 + bx * 32 + tx];
        __syncthreads();
        size_t base = (size_t)z * 512 * 512;
#pragma unroll
        for (int j = 0; j < 32; j += 8) {
            float v = t[tx][ty + j];
            __nv_bfloat16 h = __float2bfloat16(v);
            size_t o = base + (size_t)(bx * 32 + ty + j) * 512 + by * 32 + tx;
            g_Whi[o] = h;
            g_Wlo[o] = __float2bfloat16(v - __bfloat162float(h));
        }
    } else {
        int d0 = (z - 4) * 32;
        int idx = blockIdx.y * 16 + blockIdx.x;
        int hh = idx >> 5, l0 = (idx & 31) * 32;
#pragma unroll
        for (int j = 0; j < 32; j += 8)
            t[ty + j][tx] = rel[(size_t)(hh * 64 + d0 + ty + j) * 1024 + l0 + tx];
        __syncthreads();
#pragma unroll
        for (int j = 0; j < 32; j += 8)
            g_relT[(size_t)(hh * 1024 + l0 + ty + j) * 64 + d0 + tx] =
                __float2bfloat16(t[tx][ty + j]);
    }
}

// ---------------- merged QKV projection GEMM (unchanged) ----------------
__global__ __launch_bounds__(128) void gemm_qkv()
{
    __shared__ __nv_bfloat16 sA[2][2][64 * LDA];
    __shared__ __nv_bfloat16 sB[2][2][64 * LDA];
    const int z = blockIdx.z;
    const __nv_bfloat16* Ah = (z == 0) ? g_A0h : (z == 1) ? g_A1h : g_A2h;
    const __nv_bfloat16* Al = (z == 0) ? g_A0l : (z == 1) ? g_A1l : g_A2l;
    const __nv_bfloat16* Bh = g_Whi + (size_t)z * 512 * 512;
    const __nv_bfloat16* Bl = g_Wlo + (size_t)z * 512 * 512;
    const int tid = threadIdx.x;
    const int wid = tid >> 5, lane = tid & 31;
    const int m_blk = blockIdx.y * 64, n_blk = blockIdx.x * 64;
    const int wm = (wid >> 1) * 32, wn = (wid & 1) * 32;

    float acc[2][4][4] = {};

    auto load_stage = [&](int stg, int k0) {
        int st = stg & 1;
        int r1 = tid >> 2, sg = tid & 3;
#pragma unroll
        for (int i = 0; i < 2; i++) {
            int r = r1 + i * 32;
            uint32_t off = (uint32_t)(r * LDA + sg * 8) * 2;
            size_t gA = (size_t)(m_blk + r) * 512 + k0 + sg * 8;
            size_t gB = (size_t)(n_blk + r) * 512 + k0 + sg * 8;
            CP16(smaddr(&sA[st][0][0]) + off, Ah + gA);
            CP16(smaddr(&sA[st][1][0]) + off, Al + gA);
            CP16(smaddr(&sB[st][0][0]) + off, Bh + gB);
            CP16(smaddr(&sB[st][1][0]) + off, Bl + gB);
        }
    };

    load_stage(0, 0);
    CP_COMMIT();

    for (int s = 0; s < 16; s++) {
        if (s < 15) {
            load_stage(s + 1, (s + 1) * 32);
            CP_COMMIT();
            asm volatile("cp.async.wait_group 1;");
        } else {
            asm volatile("cp.async.wait_group 0;");
        }
        __syncthreads();
        int st = s & 1;
#pragma unroll
        for (int kk = 0; kk < 2; kk++) {
            uint32_t ah[2][4], al[2][4], bhf[2][4], blf[2][4];
#pragma unroll
            for (int im = 0; im < 2; im++) {
                int r = wm + im * 16 + (lane & 15);
                int cc = ((lane >> 4) << 3) + kk * 16;
                ldm_x4(ah[im], smaddr(&sA[st][0][r * LDA + cc]));
                ldm_x4(al[im], smaddr(&sA[st][1][r * LDA + cc]));
            }
#pragma unroll
            for (int bt = 0; bt < 2; bt++) {
                int r = wn + bt * 16 + ((lane >> 4) << 3) + (lane & 7);
                int cc = (((lane >> 3) & 1) << 3) + kk * 16;
                ldm_x4(bhf[bt], smaddr(&sB[st][0][r * LDA + cc]));
                ldm_x4(blf[bt], smaddr(&sB[st][1][r * LDA + cc]));
            }
#pragma unroll
            for (int im = 0; im < 2; im++)
#pragma unroll
                for (int in = 0; in < 4; in++) {
                    uint32_t bh2[2] = { bhf[in >> 1][(in & 1) * 2], bhf[in >> 1][(in & 1) * 2 + 1] };
                    uint32_t bl2[2] = { blf[in >> 1][(in & 1) * 2], blf[in >> 1][(in & 1) * 2 + 1] };
                    mma16816(acc[im][in], ah[im], bh2);
                    mma16816(acc[im][in], ah[im], bl2);
                    mma16816(acc[im][in], al[im], bh2);
                }
        }
        __syncthreads();
    }

    __nv_bfloat16* Chi = (z == 0) ? g_Qh : (z == 1) ? g_Kh : g_Vth;
    __nv_bfloat16* Clo = (z == 0) ? g_Ql : (z == 1) ? g_Kl : g_Vtl;
#pragma unroll
    for (int im = 0; im < 2; im++)
#pragma unroll
        for (int in = 0; in < 4; in++) {
            int mo = m_blk + wm + im * 16 + (lane >> 2);
            int nn = n_blk + wn + in * 8 + ((lane & 3) << 1);
            float c0 = acc[im][in][0], c1 = acc[im][in][1];
            float c2 = acc[im][in][2], c3 = acc[im][in][3];
            int b = mo >> 10, ss = mo & 1023, hh = nn >> 6, dh = nn & 63;
            if (z < 2) {
                size_t o = ((size_t)(b * 8 + hh) * 1024 + ss) * 64 + dh;
                __nv_bfloat162 h2, l2;
                split2(c0, c1, h2, l2);
                *(__nv_bfloat162*)&Chi[o] = h2; *(__nv_bfloat162*)&Clo[o] = l2;
                split2(c2, c3, h2, l2);
                *(__nv_bfloat162*)&Chi[o + 8 * 64] = h2; *(__nv_bfloat162*)&Clo[o + 8 * 64] = l2;
            } else {
                size_t o = ((size_t)(b * 8 + hh) * 64 + dh) * 1024 + ss;
                __nv_bfloat16 h;
                h = __float2bfloat16(c0); Chi[o] = h;
                Clo[o] = __float2bfloat16(c0 - __bfloat162float(h));
                h = __float2bfloat16(c1); Chi[o + 1024] = h;
                Clo[o + 1024] = __float2bfloat16(c1 - __bfloat162float(h));
                h = __float2bfloat16(c2); Chi[o + 8] = h;
                Clo[o + 8] = __float2bfloat16(c2 - __bfloat162float(h));
                h = __float2bfloat16(c3); Chi[o + 1024 + 8] = h;
                Clo[o + 1024 + 8] = __float2bfloat16(c3 - __bfloat162float(h));
            }
        }
}

// ---------------- output GEMM (unchanged) ----------------
__global__ __launch_bounds__(128) void gemm_out(float* __restrict__ C)
{
    __shared__ __nv_bfloat16 sA[2][2][64 * LDA];
    __shared__ __nv_bfloat16 sB[2][2][64 * LDA];
    const __nv_bfloat16* Ah = g_Ahi;
    const __nv_bfloat16* Al = g_Alo;
    const __nv_bfloat16* Bh = g_Whi + (size_t)3 * 512 * 512;
    const __nv_bfloat16* Bl = g_Wlo + (size_t)3 * 512 * 512;
    const int tid = threadIdx.x;
    const int wid = tid >> 5, lane = tid & 31;
    const int m_blk = blockIdx.y * 64, n_blk = blockIdx.x * 64;
    const int wm = (wid >> 1) * 32, wn = (wid & 1) * 32;

    float acc[2][4][4] = {};

    auto load_stage = [&](int stg, int k0) {
        int st = stg & 1;
        int r1 = tid >> 2, sg = tid & 3;
#pragma unroll
        for (int i = 0; i < 2; i++) {
            int r = r1 + i * 32;
            uint32_t off = (uint32_t)(r * LDA + sg * 8) * 2;
            size_t gA = (size_t)(m_blk + r) * 512 + k0 + sg * 8;
            size_t gB = (size_t)(n_blk + r) * 512 + k0 + sg * 8;
            CP16(smaddr(&sA[st][0][0]) + off, Ah + gA);
            CP16(smaddr(&sA[st][1][0]) + off, Al + gA);
            CP16(smaddr(&sB[st][0][0]) + off, Bh + gB);
            CP16(smaddr(&sB[st][1][0]) + off, Bl + gB);
        }
    };

    load_stage(0, 0);
    CP_COMMIT();

    for (int s = 0; s < 16; s++) {
        if (s < 15) {
            load_stage(s + 1, (s + 1) * 32);
            CP_COMMIT();
            asm volatile("cp.async.wait_group 1;");
        } else {
            asm volatile("cp.async.wait_group 0;");
        }
        __syncthreads();
        int st = s & 1;
#pragma unroll
        for (int kk = 0; kk < 2; kk++) {
            uint32_t ah[2][4], al[2][4], bhf[2][4], blf[2][4];
#pragma unroll
            for (int im = 0; im < 2; im++) {
                int r = wm + im * 16 + (lane & 15);
                int cc = ((lane >> 4) << 3) + kk * 16;
                ldm_x4(ah[im], smaddr(&sA[st][0][r * LDA + cc]));
                ldm_x4(al[im], smaddr(&sA[st][1][r * LDA + cc]));
            }
#pragma unroll
            for (int bt = 0; bt < 2; bt++) {
                int r = wn + bt * 16 + ((lane >> 4) << 3) + (lane & 7);
                int cc = (((lane >> 3) & 1) << 3) + kk * 16;
                ldm_x4(bhf[bt], smaddr(&sB[st][0][r * LDA + cc]));
                ldm_x4(blf[bt], smaddr(&sB[st][1][r * LDA + cc]));
            }
#pragma unroll
            for (int im = 0; im < 2; im++)
#pragma unroll
                for (int in = 0; in < 4; in++) {
                    uint32_t bh2[2] = { bhf[in >> 1][(in & 1) * 2], bhf[in >> 1][(in & 1) * 2 + 1] };
                    uint32_t bl2[2] = { blf[in >> 1][(in & 1) * 2], blf[in >> 1][(in & 1) * 2 + 1] };
                    mma16816(acc[im][in], ah[im], bh2);
                    mma16816(acc[im][in], ah[im], bl2);
                    mma16816(acc[im][in], al[im], bh2);
                }
        }
        __syncthreads();
    }

#pragma unroll
    for (int im = 0; im < 2; im++)
#pragma unroll
        for (int in = 0; in < 4; in++) {
            int mo = m_blk + wm + im * 16 + (lane >> 2);
            int nn = n_blk + wn + in * 8 + ((lane & 3) << 1);
            *(float2*)&C[(size_t)mo * 512 + nn] = make_float2(acc[im][in][0], acc[im][in][1]);
            *(float2*)&C[(size_t)(mo + 8) * 512 + nn] = make_float2(acc[im][in][2], acc[im][in][3]);
        }
}

// ---------------- attention: BM=128, 16 rows/warp, fully pipelined loads ----------------
__global__ __launch_bounds__(256, 1) void attn_kernel()
{
    extern __shared__ __align__(16) char smc[];
    __nv_bfloat16* sQe = (__nv_bfloat16*)(smc + OFF_QE);
    const int tid = threadIdx.x;
    const int wid = tid >> 5, lane = tid & 31;
    const int qi = 7 - blockIdx.x;        // heavy first
    const int bh = blockIdx.y;
    const int h = bh & 7, b = bh >> 3;
    const int i0 = qi * 128;
    const int wm = wid * 16;
    const int rl = lane >> 2;
    const int qoff = (lane & 3) << 1;
    const uint32_t smb = smaddr(smc);
    const int ntiles = qi + 1;

    auto issueK = [&](int jt) {
        int st = jt & 1, j0 = jt * 128;
        uint32_t kh = smb + OFF_K + st * 36864, kl = kh + 18432;
#pragma unroll
        for (int it = 0; it < 4; it++) {
            int idx = tid + it * 256, r = idx >> 3, sg = idx & 7;
            size_t gk = ((size_t)bh * 1024 + j0 + r) * 64 + sg * 8;
            uint32_t off = (uint32_t)(r * 72 + sg * 8) * 2;
            CP16(kh + off, g_Kh + gk);
            CP16(kl + off, g_Kl + gk);
        }
    };
    auto issueRel = [&](int jt) {
        int st = jt & 1, j0 = jt * 128;
        int lmin = 896 - i0 + j0;
        uint32_t rp = smb + OFF_REL + st * 36864;
#pragma unroll
        for (int it = 0; it < 8; it++) {
            int idx = tid + it * 256, x = idx >> 3, sg = idx & 7;
            int l = lmin + x;
            int n = (l <= 1023) ? 16 : 0;
            int lc = (l <= 1023) ? l : 1023;
            CP16P(rp + (uint32_t)(x * 72 + sg * 8) * 2,
                  g_relT + ((size_t)h * 1024 + lc) * 64 + sg * 8, n);
        }
    };
    auto issueV = [&](int jt) {
        int j0 = jt * 128;
        uint32_t vh = smb + OFF_V, vl = vh + 17408;
#pragma unroll
        for (int it = 0; it < 4; it++) {
            int idx = tid + it * 256, dd = idx >> 4, sg = idx & 15;
            size_t gv = ((size_t)bh * 64 + dd) * 1024 + j0 + sg * 8;
            uint32_t off = (uint32_t)(dd * 136 + sg * 8) * 2;
            CP16(vh + off, g_Vth + gv);
            CP16(vl + off, g_Vtl + gv);
        }
    };

    issueK(0);
    CP_COMMIT();

    // ---- prologue: Q via rel-stage area (overwritten later by rel cp.async) ----
    __nv_bfloat16* sQh_p = (__nv_bfloat16*)(smc + OFF_REL);
    __nv_bfloat16* sQl_p = (__nv_bfloat16*)(smc + OFF_REL + 18432);
#pragma unroll
    for (int it = 0; it < 4; it++) {
        int idx = tid + it * 256, r = idx >> 3, sg = idx & 7;
        size_t gq = ((size_t)bh * 1024 + i0 + r) * 64 + sg * 8;
        *(uint4*)&sQh_p[r * 72 + sg * 8] = *(const uint4*)&g_Qh[gq];
        *(uint4*)&sQl_p[r * 72 + sg * 8] = *(const uint4*)&g_Ql[gq];
    }
    __syncthreads();
    uint32_t aQh[4][4], aQl[4][4];
#pragma unroll
    for (int kk = 0; kk < 4; kk++) {
        int r = wm + (lane & 15);
        int cc = ((lane >> 4) << 3) + kk * 16;
        ldm_x4(aQh[kk], smaddr(&sQh_p[r * 72 + cc]));
        ldm_x4(aQl[kk], smaddr(&sQl_p[r * 72 + cc]));
    }
    __syncthreads();

    issueRel(0);
    CP_COMMIT();
    issueV(0);
    CP_COMMIT();

    float mrow[2] = {-3.0e38f, -3.0e38f};
    float lrow[2] = {0.f, 0.f};
    float oacc[8][4] = {};

    for (int jt = 0; jt < ntiles; jt++) {
        asm volatile("cp.async.wait_group 1;");   // K_jt + rel_jt done; V_jt may pend
        __syncthreads();
        const int st = jt & 1;
        const int j0 = jt * 128;
        __nv_bfloat16* sKh  = (__nv_bfloat16*)(smc + OFF_K + st * 36864);
        __nv_bfloat16* sKl  = (__nv_bfloat16*)(smc + OFF_K + st * 36864 + 18432);
        __nv_bfloat16* sRel = (__nv_bfloat16*)(smc + OFF_REL + st * 36864);
        __nv_bfloat16* sVh  = (__nv_bfloat16*)(smc + OFF_V);
        __nv_bfloat16* sVl  = (__nv_bfloat16*)(smc + OFF_V + 17408);
        const int xs = 112 - wm;

        // ---- QE: my 16 rows x 144 window, local (shifted) storage ----
#pragma unroll
        for (int p = 0; p < 2; p++) {
            const int nb_cnt = (p == 0) ? 10 : 8;
            const int xoff = (p == 0) ? 0 : 80;
            float eacc[10][4] = {};
#pragma unroll
            for (int kk = 0; kk < 4; kk++) {
                uint32_t br[5][4];
                const int nld = (p == 0) ? 5 : 4;
#pragma unroll
                for (int bt = 0; bt < 5; bt++) {
                    if (bt < nld) {
                        int r = xs + xoff + bt * 16 + ((lane >> 4) << 3) + (lane & 7);
                        int cc = (((lane >> 3) & 1) << 3) + kk * 16;
                        ldm_x4(br[bt], smaddr(&sRel[r * 72 + cc]));
                    }
                }
#pragma unroll
                for (int nb = 0; nb < 10; nb++) {
                    if (nb < nb_cnt) {
                        uint32_t b2[2] = { br[nb >> 1][(nb & 1) * 2], br[nb >> 1][(nb & 1) * 2 + 1] };
                        mma16816(eacc[nb], aQh[kk], b2);
                    }
                }
            }
#pragma unroll
            for (int nb = 0; nb < 10; nb++) {
                if (nb < nb_cnt) {
                    int x = xoff + nb * 8 + qoff;       // local coordinate
                    int i = wm + rl;
                    *(__nv_bfloat162*)&sQe[i * QE_STRIDE + x] =
                        __nv_bfloat162(__float2bfloat16(eacc[nb][0]),
                                       __float2bfloat16(eacc[nb][1]));
                    *(__nv_bfloat162*)&sQe[(i + 8) * QE_STRIDE + x] =
                        __nv_bfloat162(__float2bfloat16(eacc[nb][2]),
                                       __float2bfloat16(eacc[nb][3]));
                }
            }
        }
        __syncwarp();

        // ---- QK^T (bf16x3): my 16 rows x 128 keys ----
        float sacc[16][4] = {};
#pragma unroll
        for (int nh = 0; nh < 2; nh++) {
#pragma unroll
            for (int kk = 0; kk < 4; kk++) {
                uint32_t bhf[4][4], blf[4][4];
#pragma unroll
                for (int bt = 0; bt < 4; bt++) {
                    int r = nh * 64 + bt * 16 + ((lane >> 4) << 3) + (lane & 7);
                    int cc = (((lane >> 3) & 1) << 3) + kk * 16;
                    ldm_x4(bhf[bt], smaddr(&sKh[r * 72 + cc]));
                    ldm_x4(blf[bt], smaddr(&sKl[r * 72 + cc]));
                }
#pragma unroll
                for (int in = 0; in < 8; in++) {
                    uint32_t b2h[2] = { bhf[in >> 1][(in & 1) * 2], bhf[in >> 1][(in & 1) * 2 + 1] };
                    uint32_t b2l[2] = { blf[in >> 1][(in & 1) * 2], blf[in >> 1][(in & 1) * 2 + 1] };
                    mma16816(sacc[nh * 8 + in], aQh[kk], b2h);
                    mma16816(sacc[nh * 8 + in], aQh[kk], b2l);
                    mma16816(sacc[nh * 8 + in], aQl[kk], b2h);
                }
            }
        }

        // ---- scores + warp-local softmax (qe gathered locally) ----
        float pmax[2] = {-3.0e38f, -3.0e38f};
#pragma unroll
        for (int in = 0; in < 16; in++)
#pragma unroll
            for (int hf = 0; hf < 2; hf++) {
                int iiw = rl + hf * 8;                  // row within warp
                int ii = wm + iiw;
                int tt = in * 8 + qoff;
                int lx = 15 - iiw + tt;                 // local gather index
                float q0 = __bfloat162float(sQe[ii * QE_STRIDE + lx]);
                float q1 = __bfloat162float(sQe[ii * QE_STRIDE + lx + 1]);
                float m0 = (j0 + tt     > i0 + ii) ? -1e9f : 0.f;
                float m1 = (j0 + tt + 1 > i0 + ii) ? -1e9f : 0.f;
                float s0 = (sacc[in][hf * 2]     + q0 + m0) * 0.125f;
                float s1 = (sacc[in][hf * 2 + 1] + q1 + m1) * 0.125f;
                sacc[in][hf * 2] = s0;
                sacc[in][hf * 2 + 1] = s1;
                pmax[hf] = fmaxf(pmax[hf], fmaxf(s0, s1));
            }
#pragma unroll
        for (int hf = 0; hf < 2; hf++) {
            pmax[hf] = fmaxf(pmax[hf], __shfl_xor_sync(0xffffffffu, pmax[hf], 1));
            pmax[hf] = fmaxf(pmax[hf], __shfl_xor_sync(0xffffffffu, pmax[hf], 2));
        }
        float mnew[2], alpha[2], psum[2] = {};
#pragma unroll
        for (int hf = 0; hf < 2; hf++) {
            mnew[hf] = fmaxf(mrow[hf], pmax[hf]);
            alpha[hf] = __expf(mrow[hf] - mnew[hf]);
        }
#pragma unroll
        for (int in = 0; in < 16; in++)
#pragma unroll
            for (int hf = 0; hf < 2; hf++) {
                float p0 = __expf(sacc[in][hf * 2]     - mnew[hf]);
                float p1 = __expf(sacc[in][hf * 2 + 1] - mnew[hf]);
                sacc[in][hf * 2] = p0;
                sacc[in][hf * 2 + 1] = p1;
                psum[hf] += p0 + p1;
            }
#pragma unroll
        for (int hf = 0; hf < 2; hf++) {
            psum[hf] += __shfl_xor_sync(0xffffffffu, psum[hf], 1);
            psum[hf] += __shfl_xor_sync(0xffffffffu, psum[hf], 2);
            lrow[hf] = lrow[hf] * alpha[hf] + psum[hf];
            mrow[hf] = mnew[hf];
        }
#pragma unroll
        for (int d8 = 0; d8 < 8; d8++) {
            oacc[d8][0] *= alpha[0];
            oacc[d8][1] *= alpha[0];
            oacc[d8][2] *= alpha[1];
            oacc[d8][3] *= alpha[1];
        }

        // ---- prefetch K/rel for next tile (other stages, safe) ----
        if (jt + 1 < ntiles) {
            issueK(jt + 1);
            issueRel(jt + 1);
            CP_COMMIT();
            asm volatile("cp.async.wait_group 1;");   // completes V_jt (older group)
        } else {
            asm volatile("cp.async.wait_group 0;");   // completes V_jt
        }
        __syncthreads();                              // publish V_jt

        // ---- P @ V (bf16x3) ----
#pragma unroll
        for (int kb = 0; kb < 8; kb++) {
            uint32_t aph[4], apl[4];
            aph[0] = pack_split(sacc[2 * kb][0],     sacc[2 * kb][1],     apl[0]);
            aph[1] = pack_split(sacc[2 * kb][2],     sacc[2 * kb][3],     apl[1]);
            aph[2] = pack_split(sacc[2 * kb + 1][0], sacc[2 * kb + 1][1], apl[2]);
            aph[3] = pack_split(sacc[2 * kb + 1][2], sacc[2 * kb + 1][3], apl[3]);
            uint32_t bvh[4][4], bvl[4][4];
#pragma unroll
            for (int dn = 0; dn < 4; dn++) {
                int r = dn * 16 + ((lane >> 4) << 3) + (lane & 7);
                int cc = kb * 16 + (((lane >> 3) & 1) << 3);
                ldm_x4(bvh[dn], smaddr(&sVh[r * 136 + cc]));
                ldm_x4(bvl[dn], smaddr(&sVl[r * 136 + cc]));
            }
#pragma unroll
            for (int d8 = 0; d8 < 8; d8++) {
                uint32_t b2h[2] = { bvh[d8 >> 1][(d8 & 1) * 2], bvh[d8 >> 1][(d8 & 1) * 2 + 1] };
                uint32_t b2l[2] = { bvl[d8 >> 1][(d8 & 1) * 2], bvl[d8 >> 1][(d8 & 1) * 2 + 1] };
                mma16816(oacc[d8], aph, b2h);
                mma16816(oacc[d8], apl, b2h);
                mma16816(oacc[d8], aph, b2l);
            }
        }
        __syncthreads();                              // V buffer free for next issue
        if (jt + 1 < ntiles) {
            issueV(jt + 1);
            CP_COMMIT();
        }
    }

    // ---- epilogue: my rows straight to global ----
    float inv0 = 1.f / lrow[0], inv1 = 1.f / lrow[1];
#pragma unroll
    for (int d8 = 0; d8 < 8; d8++) {
        int d = d8 * 8 + qoff;
        int r0 = wm + rl, r1 = wm + rl + 8;
        __nv_bfloat162 h2, l2;
        split2(oacc[d8][0] * inv0, oacc[d8][1] * inv0, h2, l2);
        size_t o0 = (size_t)(b * 1024 + i0 + r0) * 512 + h * 64 + d;
        *(__nv_bfloat162*)&g_Ahi[o0] = h2;
        *(__nv_bfloat162*)&g_Alo[o0] = l2;
        split2(oacc[d8][2] * inv1, oacc[d8][3] * inv1, h2, l2);
        size_t o1 = (size_t)(b * 1024 + i0 + r1) * 512 + h * 64 + d;
        *(__nv_bfloat162*)&g_Ahi[o1] = h2;
        *(__nv_bfloat162*)&g_Alo[o1] = l2;
    }
}

// ---------------- host ----------------
extern "C" void kernel_launch(void* const* d_in, const int* in_sizes, int n_in,
                              void* d_out, int out_size)
{
    const float* queries = (const float*)d_in[0];
    const float* keys    = (const float*)d_in[1];
    const float* values  = (const float*)d_in[2];
    const float* Wq = (const float*)d_in[4];
    const float* Wk = (const float*)d_in[5];
    const float* Wv = (const float*)d_in[6];
    const float* Wo = (const float*)d_in[7];
    const float* rel = (const float*)d_in[8];
    float* out = (float*)d_out;

    cudaFuncSetAttribute(attn_kernel, cudaFuncAttributeMaxDynamicSharedMemorySize, ATTN_SMEM);

    const int N4 = 4096 * 512 / 4;
    dim3 cgrid((N4 + 255) / 256, 3), cblk(256);
    dim3 mgrid(16, 16, 6), mblk(32, 8);

    conv_misc<<<mgrid, mblk>>>(Wq, Wk, Wv, Wo, rel);
    conv_act3<<<cgrid, cblk>>>(queries, keys, values, N4);

    dim3 qkvgrid(8, 64, 3), gblk(128);
    gemm_qkv<<<qkvgrid, gblk>>>();

    dim3 ga(8, 32), tb(256);
    attn_kernel<<<ga, tb, ATTN_SMEM>>>();

    dim3 ogrid(8, 64);
    gemm_out<<<ogrid, gblk>>>(out);
}

// round 15
// speedup vs baseline: 1.7743x; 1.7743x over previous
#include <cuda_runtime.h>
#include <cuda_bf16.h>
#include <cstdint>

#define S_LEN 1024
#define DHDIM 64
#define NHEADS 8
#define NBATCH 4
#define BHN (NBATCH * NHEADS)
#define LDA 40

// attn smem (BM=128 rows-per-warp config)
#define OFF_QE 0             // [128][264] bf16 = 67584; prologue: Qh@0, Ql@18432
#define OFF_KH 67584         // [128][72]
#define OFF_KL 86016
#define OFF_VH 104448        // [64][136]
#define OFF_VL 121856
#define OFF_REL 139264       // [256][72]
#define ATTN_SMEM 176128

// ---------------- scratch ----------------
__device__ __nv_bfloat16 g_Ahi[4096 * 512];
__device__ __nv_bfloat16 g_Alo[4096 * 512];
__device__ __nv_bfloat16 g_A0h[4096 * 512];
__device__ __nv_bfloat16 g_A0l[4096 * 512];
__device__ __nv_bfloat16 g_A1h[4096 * 512];
__device__ __nv_bfloat16 g_A1l[4096 * 512];
__device__ __nv_bfloat16 g_A2h[4096 * 512];
__device__ __nv_bfloat16 g_A2l[4096 * 512];
__device__ __nv_bfloat16 g_Whi[4 * 512 * 512];
__device__ __nv_bfloat16 g_Wlo[4 * 512 * 512];
__device__ __nv_bfloat16 g_Qh[BHN * S_LEN * DHDIM];
__device__ __nv_bfloat16 g_Ql[BHN * S_LEN * DHDIM];
__device__ __nv_bfloat16 g_Kh[BHN * S_LEN * DHDIM];
__device__ __nv_bfloat16 g_Kl[BHN * S_LEN * DHDIM];
__device__ __nv_bfloat16 g_Vth[BHN * DHDIM * S_LEN];   // [bh][d][t]
__device__ __nv_bfloat16 g_Vtl[BHN * DHDIM * S_LEN];
__device__ __nv_bfloat16 g_relT[NHEADS * S_LEN * DHDIM]; // [h][l][d]

// ---------------- helpers ----------------
__device__ __forceinline__ uint32_t smaddr(const void* p) {
    return (uint32_t)__cvta_generic_to_shared(p);
}
#define CP16(dst, src) \
    asm volatile("cp.async.cg.shared.global [%0], [%1], 16;" :: "r"(dst), "l"(src))

__device__ __forceinline__ void ldm_x4(uint32_t* r, uint32_t a) {
    asm volatile("ldmatrix.sync.aligned.m8n8.x4.shared.b16 {%0,%1,%2,%3}, [%4];"
                 : "=r"(r[0]), "=r"(r[1]), "=r"(r[2]), "=r"(r[3]) : "r"(a));
}
__device__ __forceinline__ void mma16816(float* c, const uint32_t* a, const uint32_t* b) {
    asm volatile("mma.sync.aligned.m16n8k16.row.col.f32.bf16.bf16.f32 "
                 "{%0,%1,%2,%3}, {%4,%5,%6,%7}, {%8,%9}, {%0,%1,%2,%3};"
                 : "+f"(c[0]), "+f"(c[1]), "+f"(c[2]), "+f"(c[3])
                 : "r"(a[0]), "r"(a[1]), "r"(a[2]), "r"(a[3]), "r"(b[0]), "r"(b[1]));
}
__device__ __forceinline__ void split2(float v0, float v1,
                                       __nv_bfloat162& h2, __nv_bfloat162& l2) {
    __nv_bfloat16 h0 = __float2bfloat16(v0), h1 = __float2bfloat16(v1);
    h2 = __nv_bfloat162(h0, h1);
    l2 = __nv_bfloat162(__float2bfloat16(v0 - __bfloat162float(h0)),
                        __float2bfloat16(v1 - __bfloat162float(h1)));
}
__device__ __forceinline__ uint32_t pack_split(float v0, float v1, uint32_t& lo) {
    __nv_bfloat162 h2, l2;
    split2(v0, v1, h2, l2);
    lo = *(uint32_t*)&l2;
    return *(uint32_t*)&h2;
}

// ---------------- convert kernels ----------------
__global__ void conv_act3(const float* __restrict__ q, const float* __restrict__ k,
                          const float* __restrict__ v, int n4) {
    int i = blockIdx.x * blockDim.x + threadIdx.x;
    if (i >= n4) return;
    int w = blockIdx.y;
    const float* x = (w == 0) ? q : (w == 1) ? k : v;
    __nv_bfloat16* hi = (w == 0) ? g_A0h : (w == 1) ? g_A1h : g_A2h;
    __nv_bfloat16* lo = (w == 0) ? g_A0l : (w == 1) ? g_A1l : g_A2l;
    float4 val = ((const float4*)x)[i];
    __nv_bfloat162 h2a, l2a, h2b, l2b;
    split2(val.x, val.y, h2a, l2a);
    split2(val.z, val.w, h2b, l2b);
    ((__nv_bfloat162*)hi)[2 * i] = h2a; ((__nv_bfloat162*)hi)[2 * i + 1] = h2b;
    ((__nv_bfloat162*)lo)[2 * i] = l2a; ((__nv_bfloat162*)lo)[2 * i + 1] = l2b;
}

__global__ void conv_misc(const float* __restrict__ W0, const float* __restrict__ W1,
                          const float* __restrict__ W2, const float* __restrict__ W3,
                          const float* __restrict__ rel) {
    __shared__ float t[32][33];
    int z = blockIdx.z;
    int tx = threadIdx.x, ty = threadIdx.y;
    if (z < 4) {
        const float* W = (z == 0) ? W0 : (z == 1) ? W1 : (z == 2) ? W2 : W3;
        int bx = blockIdx.x, by = blockIdx.y;
#pragma unroll
        for (int j = 0; j < 32; j += 8)
            t[ty + j][tx] = W[(size_t)(by * 32 + ty + j) * 512 + bx * 32 + tx];
        __syncthreads();
        size_t base = (size_t)z * 512 * 512;
#pragma unroll
        for (int j = 0; j < 32; j += 8) {
            float v = t[tx][ty + j];
            __nv_bfloat16 h = __float2bfloat16(v);
            size_t o = base + (size_t)(bx * 32 + ty + j) * 512 + by * 32 + tx;
            g_Whi[o] = h;
            g_Wlo[o] = __float2bfloat16(v - __bfloat162float(h));
        }
    } else {
        int d0 = (z - 4) * 32;
        int idx = blockIdx.y * 16 + blockIdx.x;
        int hh = idx >> 5, l0 = (idx & 31) * 32;
#pragma unroll
        for (int j = 0; j < 32; j += 8)
            t[ty + j][tx] = rel[(size_t)(hh * 64 + d0 + ty + j) * 1024 + l0 + tx];
        __syncthreads();
#pragma unroll
        for (int j = 0; j < 32; j += 8)
            g_relT[(size_t)(hh * 1024 + l0 + ty + j) * 64 + d0 + tx] =
                __float2bfloat16(t[tx][ty + j]);
    }
}

// ---------------- merged QKV projection GEMM ----------------
__global__ __launch_bounds__(128) void gemm_qkv()
{
    __shared__ __nv_bfloat16 sA[2][2][64 * LDA];
    __shared__ __nv_bfloat16 sB[2][2][64 * LDA];
    const int z = blockIdx.z;
    const __nv_bfloat16* Ah = (z == 0) ? g_A0h : (z == 1) ? g_A1h : g_A2h;
    const __nv_bfloat16* Al = (z == 0) ? g_A0l : (z == 1) ? g_A1l : g_A2l;
    const __nv_bfloat16* Bh = g_Whi + (size_t)z * 512 * 512;
    const __nv_bfloat16* Bl = g_Wlo + (size_t)z * 512 * 512;
    const int tid = threadIdx.x;
    const int wid = tid >> 5, lane = tid & 31;
    const int m_blk = blockIdx.y * 64, n_blk = blockIdx.x * 64;
    const int wm = (wid >> 1) * 32, wn = (wid & 1) * 32;

    float acc[2][4][4] = {};

    auto load_stage = [&](int stg, int k0) {
        int st = stg & 1;
        int r1 = tid >> 2, sg = tid & 3;
#pragma unroll
        for (int i = 0; i < 2; i++) {
            int r = r1 + i * 32;
            uint32_t off = (uint32_t)(r * LDA + sg * 8) * 2;
            size_t gA = (size_t)(m_blk + r) * 512 + k0 + sg * 8;
            size_t gB = (size_t)(n_blk + r) * 512 + k0 + sg * 8;
            CP16(smaddr(&sA[st][0][0]) + off, Ah + gA);
            CP16(smaddr(&sA[st][1][0]) + off, Al + gA);
            CP16(smaddr(&sB[st][0][0]) + off, Bh + gB);
            CP16(smaddr(&sB[st][1][0]) + off, Bl + gB);
        }
    };

    load_stage(0, 0);
    asm volatile("cp.async.commit_group;");

    for (int s = 0; s < 16; s++) {
        if (s < 15) {
            load_stage(s + 1, (s + 1) * 32);
            asm volatile("cp.async.commit_group;");
            asm volatile("cp.async.wait_group 1;");
        } else {
            asm volatile("cp.async.wait_group 0;");
        }
        __syncthreads();
        int st = s & 1;
#pragma unroll
        for (int kk = 0; kk < 2; kk++) {
            uint32_t ah[2][4], al[2][4], bhf[2][4], blf[2][4];
#pragma unroll
            for (int im = 0; im < 2; im++) {
                int r = wm + im * 16 + (lane & 15);
                int cc = ((lane >> 4) << 3) + kk * 16;
                ldm_x4(ah[im], smaddr(&sA[st][0][r * LDA + cc]));
                ldm_x4(al[im], smaddr(&sA[st][1][r * LDA + cc]));
            }
#pragma unroll
            for (int bt = 0; bt < 2; bt++) {
                int r = wn + bt * 16 + ((lane >> 4) << 3) + (lane & 7);
                int cc = (((lane >> 3) & 1) << 3) + kk * 16;
                ldm_x4(bhf[bt], smaddr(&sB[st][0][r * LDA + cc]));
                ldm_x4(blf[bt], smaddr(&sB[st][1][r * LDA + cc]));
            }
#pragma unroll
            for (int im = 0; im < 2; im++)
#pragma unroll
                for (int in = 0; in < 4; in++) {
                    uint32_t bh2[2] = { bhf[in >> 1][(in & 1) * 2], bhf[in >> 1][(in & 1) * 2 + 1] };
                    uint32_t bl2[2] = { blf[in >> 1][(in & 1) * 2], blf[in >> 1][(in & 1) * 2 + 1] };
                    mma16816(acc[im][in], ah[im], bh2);
                    mma16816(acc[im][in], ah[im], bl2);
                    mma16816(acc[im][in], al[im], bh2);
                }
        }
        __syncthreads();
    }

    __nv_bfloat16* Chi = (z == 0) ? g_Qh : (z == 1) ? g_Kh : g_Vth;
    __nv_bfloat16* Clo = (z == 0) ? g_Ql : (z == 1) ? g_Kl : g_Vtl;
#pragma unroll
    for (int im = 0; im < 2; im++)
#pragma unroll
        for (int in = 0; in < 4; in++) {
            int mo = m_blk + wm + im * 16 + (lane >> 2);
            int nn = n_blk + wn + in * 8 + ((lane & 3) << 1);
            float c0 = acc[im][in][0], c1 = acc[im][in][1];
            float c2 = acc[im][in][2], c3 = acc[im][in][3];
            int b = mo >> 10, ss = mo & 1023, hh = nn >> 6, dh = nn & 63;
            if (z < 2) {
                size_t o = ((size_t)(b * 8 + hh) * 1024 + ss) * 64 + dh;
                __nv_bfloat162 h2, l2;
                split2(c0, c1, h2, l2);
                *(__nv_bfloat162*)&Chi[o] = h2; *(__nv_bfloat162*)&Clo[o] = l2;
                split2(c2, c3, h2, l2);
                *(__nv_bfloat162*)&Chi[o + 8 * 64] = h2; *(__nv_bfloat162*)&Clo[o + 8 * 64] = l2;
            } else {
                size_t o = ((size_t)(b * 8 + hh) * 64 + dh) * 1024 + ss;
                __nv_bfloat16 h;
                h = __float2bfloat16(c0); Chi[o] = h;
                Clo[o] = __float2bfloat16(c0 - __bfloat162float(h));
                h = __float2bfloat16(c1); Chi[o + 1024] = h;
                Clo[o + 1024] = __float2bfloat16(c1 - __bfloat162float(h));
                h = __float2bfloat16(c2); Chi[o + 8] = h;
                Clo[o + 8] = __float2bfloat16(c2 - __bfloat162float(h));
                h = __float2bfloat16(c3); Chi[o + 1024 + 8] = h;
                Clo[o + 1024 + 8] = __float2bfloat16(c3 - __bfloat162float(h));
            }
        }
}

// ---------------- output GEMM ----------------
__global__ __launch_bounds__(128) void gemm_out(float* __restrict__ C)
{
    __shared__ __nv_bfloat16 sA[2][2][64 * LDA];
    __shared__ __nv_bfloat16 sB[2][2][64 * LDA];
    const __nv_bfloat16* Ah = g_Ahi;
    const __nv_bfloat16* Al = g_Alo;
    const __nv_bfloat16* Bh = g_Whi + (size_t)3 * 512 * 512;
    const __nv_bfloat16* Bl = g_Wlo + (size_t)3 * 512 * 512;
    const int tid = threadIdx.x;
    const int wid = tid >> 5, lane = tid & 31;
    const int m_blk = blockIdx.y * 64, n_blk = blockIdx.x * 64;
    const int wm = (wid >> 1) * 32, wn = (wid & 1) * 32;

    float acc[2][4][4] = {};

    auto load_stage = [&](int stg, int k0) {
        int st = stg & 1;
        int r1 = tid >> 2, sg = tid & 3;
#pragma unroll
        for (int i = 0; i < 2; i++) {
            int r = r1 + i * 32;
            uint32_t off = (uint32_t)(r * LDA + sg * 8) * 2;
            size_t gA = (size_t)(m_blk + r) * 512 + k0 + sg * 8;
            size_t gB = (size_t)(n_blk + r) * 512 + k0 + sg * 8;
            CP16(smaddr(&sA[st][0][0]) + off, Ah + gA);
            CP16(smaddr(&sA[st][1][0]) + off, Al + gA);
            CP16(smaddr(&sB[st][0][0]) + off, Bh + gB);
            CP16(smaddr(&sB[st][1][0]) + off, Bl + gB);
        }
    };

    load_stage(0, 0);
    asm volatile("cp.async.commit_group;");

    for (int s = 0; s < 16; s++) {
        if (s < 15) {
            load_stage(s + 1, (s + 1) * 32);
            asm volatile("cp.async.commit_group;");
            asm volatile("cp.async.wait_group 1;");
        } else {
            asm volatile("cp.async.wait_group 0;");
        }
        __syncthreads();
        int st = s & 1;
#pragma unroll
        for (int kk = 0; kk < 2; kk++) {
            uint32_t ah[2][4], al[2][4], bhf[2][4], blf[2][4];
#pragma unroll
            for (int im = 0; im < 2; im++) {
                int r = wm + im * 16 + (lane & 15);
                int cc = ((lane >> 4) << 3) + kk * 16;
                ldm_x4(ah[im], smaddr(&sA[st][0][r * LDA + cc]));
                ldm_x4(al[im], smaddr(&sA[st][1][r * LDA + cc]));
            }
#pragma unroll
            for (int bt = 0; bt < 2; bt++) {
                int r = wn + bt * 16 + ((lane >> 4) << 3) + (lane & 7);
                int cc = (((lane >> 3) & 1) << 3) + kk * 16;
                ldm_x4(bhf[bt], smaddr(&sB[st][0][r * LDA + cc]));
                ldm_x4(blf[bt], smaddr(&sB[st][1][r * LDA + cc]));
            }
#pragma unroll
            for (int im = 0; im < 2; im++)
#pragma unroll
                for (int in = 0; in < 4; in++) {
                    uint32_t bh2[2] = { bhf[in >> 1][(in & 1) * 2], bhf[in >> 1][(in & 1) * 2 + 1] };
                    uint32_t bl2[2] = { blf[in >> 1][(in & 1) * 2], blf[in >> 1][(in & 1) * 2 + 1] };
                    mma16816(acc[im][in], ah[im], bh2);
                    mma16816(acc[im][in], ah[im], bl2);
                    mma16816(acc[im][in], al[im], bh2);
                }
        }
        __syncthreads();
    }

#pragma unroll
    for (int im = 0; im < 2; im++)
#pragma unroll
        for (int in = 0; in < 4; in++) {
            int mo = m_blk + wm + im * 16 + (lane >> 2);
            int nn = n_blk + wn + in * 8 + ((lane & 3) << 1);
            *(float2*)&C[(size_t)mo * 512 + nn] = make_float2(acc[im][in][0], acc[im][in][1]);
            *(float2*)&C[(size_t)(mo + 8) * 512 + nn] = make_float2(acc[im][in][2], acc[im][in][3]);
        }
}

// ---------------- attention: BM=128, 16 rows per warp, warp-local softmax ----------------
// grid (32 bh, 8 qi-slot): qi = 7 - blockIdx.y -> globally heavy-first scheduling order
__global__ __launch_bounds__(256, 1) void attn_kernel()
{
    extern __shared__ __align__(16) char smc[];
    __nv_bfloat16* sQe  = (__nv_bfloat16*)(smc + OFF_QE);   // [128][264]; prologue Q here
    __nv_bfloat16* sKh  = (__nv_bfloat16*)(smc + OFF_KH);   // [128][72]
    __nv_bfloat16* sKl  = (__nv_bfloat16*)(smc + OFF_KL);
    __nv_bfloat16* sVh  = (__nv_bfloat16*)(smc + OFF_VH);   // [64][136]
    __nv_bfloat16* sVl  = (__nv_bfloat16*)(smc + OFF_VL);
    __nv_bfloat16* sRel = (__nv_bfloat16*)(smc + OFF_REL);  // [256][72]

    const int tid = threadIdx.x;
    const int wid = tid >> 5, lane = tid & 31;
    const int qi = 7 - blockIdx.y;        // slow axis -> global heavy-first
    const int bh = blockIdx.x;
    const int h = bh & 7, b = bh >> 3;
    const int i0 = qi * 128;
    const int wm = wid * 16;              // my 16 rows
    const int rl = lane >> 2;
    const int qoff = (lane & 3) << 1;
    const int xs = 112 - wm;              // QE band window start (>=0)

    // ---- prologue: Q -> smem (transient), hoist fragments ----
    __nv_bfloat16* sQh_p = (__nv_bfloat16*)(smc + OFF_QE);
    __nv_bfloat16* sQl_p = (__nv_bfloat16*)(smc + OFF_QE + 18432);
#pragma unroll
    for (int it = 0; it < 4; it++) {
        int idx = tid + it * 256, r = idx >> 3, sg = idx & 7;
        size_t gq = ((size_t)bh * 1024 + i0 + r) * 64 + sg * 8;
        *(uint4*)&sQh_p[r * 72 + sg * 8] = *(const uint4*)&g_Qh[gq];
        *(uint4*)&sQl_p[r * 72 + sg * 8] = *(const uint4*)&g_Ql[gq];
    }
    __syncthreads();
    uint32_t aQh[4][4], aQl[4][4];
#pragma unroll
    for (int kk = 0; kk < 4; kk++) {
        int r = wm + (lane & 15);
        int cc = ((lane >> 4) << 3) + kk * 16;
        ldm_x4(aQh[kk], smaddr(&sQh_p[r * 72 + cc]));
        ldm_x4(aQl[kk], smaddr(&sQl_p[r * 72 + cc]));
    }

    float mrow[2] = {-3.0e38f, -3.0e38f};
    float lrow[2] = {0.f, 0.f};
    float oacc[8][4] = {};
    const int ntiles = qi + 1;

    for (int jt = 0; jt < ntiles; jt++) {
        const int j0 = jt * 128;
        const int lmin = 896 - i0 + j0;
        __syncthreads();                  // protect K/V/rel (and retire Q smem on jt=0)
        // K [128][72] hi/lo
#pragma unroll
        for (int it = 0; it < 4; it++) {
            int idx = tid + it * 256, r = idx >> 3, sg = idx & 7;
            size_t gk = ((size_t)bh * 1024 + j0 + r) * 64 + sg * 8;
            *(uint4*)&sKh[r * 72 + sg * 8] = *(const uint4*)&g_Kh[gk];
            *(uint4*)&sKl[r * 72 + sg * 8] = *(const uint4*)&g_Kl[gk];
        }
        // V [64][136] hi/lo
#pragma unroll
        for (int it = 0; it < 4; it++) {
            int idx = tid + it * 256, dd = idx >> 4, sg = idx & 15;
            size_t gv = ((size_t)bh * 64 + dd) * 1024 + j0 + sg * 8;
            *(uint4*)&sVh[dd * 136 + sg * 8] = *(const uint4*)&g_Vth[gv];
            *(uint4*)&sVl[dd * 136 + sg * 8] = *(const uint4*)&g_Vtl[gv];
        }
        // rel [256][72], guard l <= 1023
#pragma unroll
        for (int it = 0; it < 8; it++) {
            int idx = tid + it * 256, x = idx >> 3, sg = idx & 7;
            int l = lmin + x;
            uint4 v = make_uint4(0, 0, 0, 0);
            if (l <= 1023)
                v = *(const uint4*)&g_relT[((size_t)h * 1024 + l) * 64 + sg * 8];
            *(uint4*)&sRel[x * 72 + sg * 8] = v;
        }
        __syncthreads();                  // published

        // ---- QE: my 16 rows x 144-wide window, 2 passes (10 + 8 n8 blocks) ----
#pragma unroll
        for (int p = 0; p < 2; p++) {
            const int nb_cnt = (p == 0) ? 10 : 8;
            const int xoff = (p == 0) ? 0 : 80;
            float eacc[10][4] = {};
#pragma unroll
            for (int kk = 0; kk < 4; kk++) {
                uint32_t br[5][4];
                const int nld = (p == 0) ? 5 : 4;
#pragma unroll
                for (int bt = 0; bt < 5; bt++) {
                    if (bt < nld) {
                        int r = xs + xoff + bt * 16 + ((lane >> 4) << 3) + (lane & 7);
                        int cc = (((lane >> 3) & 1) << 3) + kk * 16;
                        ldm_x4(br[bt], smaddr(&sRel[r * 72 + cc]));
                    }
                }
#pragma unroll
                for (int nb = 0; nb < 10; nb++) {
                    if (nb < nb_cnt) {
                        uint32_t b2[2] = { br[nb >> 1][(nb & 1) * 2], br[nb >> 1][(nb & 1) * 2 + 1] };
                        mma16816(eacc[nb], aQh[kk], b2);
                    }
                }
            }
#pragma unroll
            for (int nb = 0; nb < 10; nb++) {
                if (nb < nb_cnt) {
                    int x = xs + xoff + nb * 8 + qoff;
                    int i = wm + rl;
                    *(__nv_bfloat162*)&sQe[i * 264 + x] =
                        __nv_bfloat162(__float2bfloat16(eacc[nb][0]),
                                       __float2bfloat16(eacc[nb][1]));
                    *(__nv_bfloat162*)&sQe[(i + 8) * 264 + x] =
                        __nv_bfloat162(__float2bfloat16(eacc[nb][2]),
                                       __float2bfloat16(eacc[nb][3]));
                }
            }
        }
        __syncwarp();

        // ---- QK^T (bf16x3): my 16 rows x 128 keys ----
        float sacc[16][4] = {};
#pragma unroll
        for (int nh = 0; nh < 2; nh++) {
#pragma unroll
            for (int kk = 0; kk < 4; kk++) {
                uint32_t bhf[4][4], blf[4][4];
#pragma unroll
                for (int bt = 0; bt < 4; bt++) {
                    int r = nh * 64 + bt * 16 + ((lane >> 4) << 3) + (lane & 7);
                    int cc = (((lane >> 3) & 1) << 3) + kk * 16;
                    ldm_x4(bhf[bt], smaddr(&sKh[r * 72 + cc]));
                    ldm_x4(blf[bt], smaddr(&sKl[r * 72 + cc]));
                }
#pragma unroll
                for (int in = 0; in < 8; in++) {
                    uint32_t b2h[2] = { bhf[in >> 1][(in & 1) * 2], bhf[in >> 1][(in & 1) * 2 + 1] };
                    uint32_t b2l[2] = { blf[in >> 1][(in & 1) * 2], blf[in >> 1][(in & 1) * 2 + 1] };
                    mma16816(sacc[nh * 8 + in], aQh[kk], b2h);
                    mma16816(sacc[nh * 8 + in], aQh[kk], b2l);
                    mma16816(sacc[nh * 8 + in], aQl[kk], b2h);
                }
            }
        }

        // ---- scores + warp-local softmax ----
        float pmax[2] = {-3.0e38f, -3.0e38f};
#pragma unroll
        for (int in = 0; in < 16; in++)
#pragma unroll
            for (int hf = 0; hf < 2; hf++) {
                int ii = wm + rl + hf * 8;
                int tt = in * 8 + qoff;
                float q0 = __bfloat162float(sQe[ii * 264 + (127 - ii + tt)]);
                float q1 = __bfloat162float(sQe[ii * 264 + (127 - ii + tt + 1)]);
                float m0 = (j0 + tt     > i0 + ii) ? -1e9f : 0.f;
                float m1 = (j0 + tt + 1 > i0 + ii) ? -1e9f : 0.f;
                float s0 = (sacc[in][hf * 2]     + q0 + m0) * 0.125f;
                float s1 = (sacc[in][hf * 2 + 1] + q1 + m1) * 0.125f;
                sacc[in][hf * 2] = s0;
                sacc[in][hf * 2 + 1] = s1;
                pmax[hf] = fmaxf(pmax[hf], fmaxf(s0, s1));
            }
#pragma unroll
        for (int hf = 0; hf < 2; hf++) {
            pmax[hf] = fmaxf(pmax[hf], __shfl_xor_sync(0xffffffffu, pmax[hf], 1));
            pmax[hf] = fmaxf(pmax[hf], __shfl_xor_sync(0xffffffffu, pmax[hf], 2));
        }
        float mnew[2], alpha[2], psum[2] = {};
#pragma unroll
        for (int hf = 0; hf < 2; hf++) {
            mnew[hf] = fmaxf(mrow[hf], pmax[hf]);
            alpha[hf] = __expf(mrow[hf] - mnew[hf]);
        }
#pragma unroll
        for (int in = 0; in < 16; in++)
#pragma unroll
            for (int hf = 0; hf < 2; hf++) {
                float p0 = __expf(sacc[in][hf * 2]     - mnew[hf]);
                float p1 = __expf(sacc[in][hf * 2 + 1] - mnew[hf]);
                sacc[in][hf * 2] = p0;
                sacc[in][hf * 2 + 1] = p1;
                psum[hf] += p0 + p1;
            }
#pragma unroll
        for (int hf = 0; hf < 2; hf++) {
            psum[hf] += __shfl_xor_sync(0xffffffffu, psum[hf], 1);
            psum[hf] += __shfl_xor_sync(0xffffffffu, psum[hf], 2);
            lrow[hf] = lrow[hf] * alpha[hf] + psum[hf];
            mrow[hf] = mnew[hf];
        }
#pragma unroll
        for (int d8 = 0; d8 < 8; d8++) {
            oacc[d8][0] *= alpha[0];
            oacc[d8][1] *= alpha[0];
            oacc[d8][2] *= alpha[1];
            oacc[d8][3] *= alpha[1];
        }

        // ---- P @ V (bf16x3), per k16 block ----
#pragma unroll
        for (int kb = 0; kb < 8; kb++) {
            uint32_t aph[4], apl[4];
            aph[0] = pack_split(sacc[2 * kb][0],     sacc[2 * kb][1],     apl[0]);
            aph[1] = pack_split(sacc[2 * kb][2],     sacc[2 * kb][3],     apl[1]);
            aph[2] = pack_split(sacc[2 * kb + 1][0], sacc[2 * kb + 1][1], apl[2]);
            aph[3] = pack_split(sacc[2 * kb + 1][2], sacc[2 * kb + 1][3], apl[3]);
            uint32_t bvh[4][4], bvl[4][4];
#pragma unroll
            for (int dn = 0; dn < 4; dn++) {
                int r = dn * 16 + ((lane >> 4) << 3) + (lane & 7);
                int cc = kb * 16 + (((lane >> 3) & 1) << 3);
                ldm_x4(bvh[dn], smaddr(&sVh[r * 136 + cc]));
                ldm_x4(bvl[dn], smaddr(&sVl[r * 136 + cc]));
            }
#pragma unroll
            for (int d8 = 0; d8 < 8; d8++) {
                uint32_t b2h[2] = { bvh[d8 >> 1][(d8 & 1) * 2], bvh[d8 >> 1][(d8 & 1) * 2 + 1] };
                uint32_t b2l[2] = { bvl[d8 >> 1][(d8 & 1) * 2], bvl[d8 >> 1][(d8 & 1) * 2 + 1] };
                mma16816(oacc[d8], aph, b2h);
                mma16816(oacc[d8], apl, b2h);
                mma16816(oacc[d8], aph, b2l);
            }
        }
    }

    // ---- epilogue: my rows straight to global ----
    float inv0 = 1.f / lrow[0], inv1 = 1.f / lrow[1];
#pragma unroll
    for (int d8 = 0; d8 < 8; d8++) {
        int d = d8 * 8 + qoff;
        int r0 = wm + rl, r1 = wm + rl + 8;
        __nv_bfloat162 h2, l2;
        split2(oacc[d8][0] * inv0, oacc[d8][1] * inv0, h2, l2);
        size_t o0 = (size_t)(b * 1024 + i0 + r0) * 512 + h * 64 + d;
        *(__nv_bfloat162*)&g_Ahi[o0] = h2;
        *(__nv_bfloat162*)&g_Alo[o0] = l2;
        split2(oacc[d8][2] * inv1, oacc[d8][3] * inv1, h2, l2);
        size_t o1 = (size_t)(b * 1024 + i0 + r1) * 512 + h * 64 + d;
        *(__nv_bfloat162*)&g_Ahi[o1] = h2;
        *(__nv_bfloat162*)&g_Alo[o1] = l2;
    }
}

// ---------------- host ----------------
extern "C" void kernel_launch(void* const* d_in, const int* in_sizes, int n_in,
                              void* d_out, int out_size)
{
    const float* queries = (const float*)d_in[0];
    const float* keys    = (const float*)d_in[1];
    const float* values  = (const float*)d_in[2];
    const float* Wq = (const float*)d_in[4];
    const float* Wk = (const float*)d_in[5];
    const float* Wv = (const float*)d_in[6];
    const float* Wo = (const float*)d_in[7];
    const float* rel = (const float*)d_in[8];
    float* out = (float*)d_out;

    cudaFuncSetAttribute(attn_kernel, cudaFuncAttributeMaxDynamicSharedMemorySize, ATTN_SMEM);

    const int N4 = 4096 * 512 / 4;
    dim3 cgrid((N4 + 255) / 256, 3), cblk(256);
    dim3 mgrid(16, 16, 6), mblk(32, 8);

    conv_misc<<<mgrid, mblk>>>(Wq, Wk, Wv, Wo, rel);
    conv_act3<<<cgrid, cblk>>>(queries, keys, values, N4);

    dim3 qkvgrid(8, 64, 3), gblk(128);
    gemm_qkv<<<qkvgrid, gblk>>>();

    dim3 ga(32, 8), tb(256);
    attn_kernel<<<ga, tb, ATTN_SMEM>>>();

    dim3 ogrid(8, 64);
    gemm_out<<<ogrid, gblk>>>(out);
}